// round 5
// baseline (speedup 1.0000x reference)
#include <cuda_runtime.h>
#include <cstdint>
#include <cstddef>

#define Bb 16
#define Tt 4096
#define Cc 64
#define Hh 128

// scratch for q, k, v projections ([B][T][H] each, ~33.5MB each)
__device__ float g_q[Bb * Tt * Hh];
__device__ float g_k[Bb * Tt * Hh];
__device__ float g_v[Bb * Tt * Hh];

// ---------------- packed f32x2 helpers (sm_100+ PTX) ----------------
__device__ __forceinline__ unsigned long long pk2(float lo, float hi) {
    unsigned long long r;
    asm("mov.b64 %0, {%1, %2};" : "=l"(r) : "f"(lo), "f"(hi));
    return r;
}
__device__ __forceinline__ void fma2(unsigned long long& d, unsigned long long a,
                                     unsigned long long b) {
    asm("fma.rn.f32x2 %0, %1, %2, %0;" : "+l"(d) : "l"(a), "l"(b));
}
__device__ __forceinline__ void mul2(unsigned long long& d, unsigned long long a) {
    asm("mul.rn.f32x2 %0, %0, %1;" : "+l"(d) : "l"(a));
}
__device__ __forceinline__ float2 upk2(unsigned long long v) {
    float2 r;
    asm("mov.b64 {%0, %1}, %2;" : "=f"(r.x), "=f"(r.y) : "l"(v));
    return r;
}

// ---------------- projection: out[b,t,h] = sum_c x[b,t,c] * W[c,h] ----------------
#define PROJ_ROWS 16
__global__ __launch_bounds__(128) void proj_kernel(
    const float* __restrict__ x, const float* __restrict__ Wk,
    const float* __restrict__ Wq, const float* __restrict__ Wv)
{
    const int which = blockIdx.y;
    const float* W = (which == 0) ? Wq : (which == 1) ? Wk : Wv;
    float* out = (which == 0) ? g_q : (which == 1) ? g_k : g_v;
    // fold softmax scale (C^-0.5 = 0.125, n_embd NOT head_size) into q
    const float oscale = (which == 0) ? 0.125f : 1.0f;

    const int h = threadIdx.x;
    float w[Cc];
#pragma unroll
    for (int c = 0; c < Cc; c++) w[c] = W[c * Hh + h];

    __shared__ float xs[PROJ_ROWS][Cc];
    const int row0 = blockIdx.x * PROJ_ROWS;
    const float4* xg = (const float4*)(x + (size_t)row0 * Cc);
#pragma unroll
    for (int i = threadIdx.x; i < PROJ_ROWS * Cc / 4; i += 128)
        ((float4*)xs)[i] = xg[i];
    __syncthreads();

#pragma unroll
    for (int r = 0; r < PROJ_ROWS; r++) {
        float acc = 0.f;
#pragma unroll
        for (int c = 0; c < Cc; c++) acc += xs[r][c] * w[c];
        out[(size_t)(row0 + r) * Hh + h] = acc * oscale;
    }
}

// ---------------- flash attention (non-causal, online softmax) ----------------
#define BM 128           // queries per block
#define BN 64            // keys per tile
#define NTH 256
#define KS_STRIDE 68     // padded stride for transposed K tile [d][k];
                         // MUST be a multiple of 4 so row bases stay 16B-aligned
                         // for the LDS.128 in the score loop (65 trapped with
                         // "misaligned address" on odd d)

__global__ __launch_bounds__(NTH, 1) void attn_kernel(float* __restrict__ out)
{
    extern __shared__ float sm[];
    float* Qs = sm;                          // BM*Hh          = 16384 floats
    float* Ks = Qs + BM * Hh;                // Hh*KS_STRIDE   =  8704 (K transposed [d][k])
    float* Vs = Ks + Hh * KS_STRIDE;         // BN*Hh          =  8192
    float* Ps = Vs + BN * Hh;                // BM*BN          =  8192

    const int tid = threadIdx.x;
    const int ty = tid >> 4;                 // 0..15 -> query group (8 queries)
    const int tx = tid & 15;                 // 0..15 -> 4 keys (score) / 8 dims (PV)
    const int b = blockIdx.y;
    const int q0 = blockIdx.x * BM;
    const int qb = ty * 8;
    const int kb = tx * 4;

    const float* qg = g_q + ((size_t)b * Tt + q0) * Hh;
    const float* kg = g_k + (size_t)b * Tt * Hh;
    const float* vg = g_v + (size_t)b * Tt * Hh;

    // load Q tile (straight float4 copy)
    for (int i = tid; i < BM * Hh / 4; i += NTH)
        ((float4*)Qs)[i] = ((const float4*)qg)[i];

    float m[8], l[8];
    unsigned long long O2[8][4];             // 8 queries x 8 dims as f32x2 pairs
#pragma unroll
    for (int i = 0; i < 8; i++) {
        m[i] = -1e30f;
        l[i] = 0.f;
#pragma unroll
        for (int j = 0; j < 4; j++) O2[i][j] = 0ull;
    }

    for (int kt = 0; kt < Tt / BN; kt++) {
        __syncthreads();  // previous iter done with Ks/Vs/Ps (also covers Q load, iter 0)

        // load K tile transposed into [d][k] (stride 68)
        const float4* kg4 = (const float4*)(kg + (size_t)kt * BN * Hh);
        for (int i = tid; i < BN * Hh / 4; i += NTH) {
            const int kk = i >> 5;           // key row 0..63
            const int d = (i & 31) * 4;      // dim 0..124
            const float4 t = kg4[i];
            Ks[(d + 0) * KS_STRIDE + kk] = t.x;
            Ks[(d + 1) * KS_STRIDE + kk] = t.y;
            Ks[(d + 2) * KS_STRIDE + kk] = t.z;
            Ks[(d + 3) * KS_STRIDE + kk] = t.w;
        }
        // load V tile (row-major copy)
        const float4* vg4 = (const float4*)(vg + (size_t)kt * BN * Hh);
        for (int i = tid; i < BN * Hh / 4; i += NTH)
            ((float4*)Vs)[i] = vg4[i];
        __syncthreads();

        // ---- scores: s[8 queries][4 keys], accumulated as f32x2 pairs ----
        unsigned long long s2[8][2];
#pragma unroll
        for (int i = 0; i < 8; i++) { s2[i][0] = 0ull; s2[i][1] = 0ull; }

#pragma unroll 4
        for (int d4 = 0; d4 < Hh / 4; d4++) {
            float4 qv[8];
#pragma unroll
            for (int i = 0; i < 8; i++)
                qv[i] = *(const float4*)&Qs[(qb + i) * Hh + d4 * 4];
#pragma unroll
            for (int dd = 0; dd < 4; dd++) {
                const float4 kv = *(const float4*)&Ks[(d4 * 4 + dd) * KS_STRIDE + kb];
                const unsigned long long k01 = pk2(kv.x, kv.y);
                const unsigned long long k23 = pk2(kv.z, kv.w);
#pragma unroll
                for (int i = 0; i < 8; i++) {
                    const float qs = (dd == 0) ? qv[i].x : (dd == 1) ? qv[i].y
                                   : (dd == 2) ? qv[i].z : qv[i].w;
                    const unsigned long long qq = pk2(qs, qs);
                    fma2(s2[i][0], qq, k01);
                    fma2(s2[i][1], qq, k23);
                }
            }
        }

        // ---- online softmax update (row stats via width-16 shfl butterflies) ----
#pragma unroll
        for (int i = 0; i < 8; i++) {
            const float2 a = upk2(s2[i][0]);
            const float2 c = upk2(s2[i][1]);
            float tm = fmaxf(fmaxf(a.x, a.y), fmaxf(c.x, c.y));
#pragma unroll
            for (int off = 8; off >= 1; off >>= 1)
                tm = fmaxf(tm, __shfl_xor_sync(0xffffffffu, tm, off, 16));
            const float mn = fmaxf(m[i], tm);
            const float corr = __expf(m[i] - mn);
            const float p0 = __expf(a.x - mn);
            const float p1 = __expf(a.y - mn);
            const float p2 = __expf(c.x - mn);
            const float p3 = __expf(c.y - mn);
            float rs = (p0 + p1) + (p2 + p3);
#pragma unroll
            for (int off = 8; off >= 1; off >>= 1)
                rs += __shfl_xor_sync(0xffffffffu, rs, off, 16);
            l[i] = l[i] * corr + rs;
            m[i] = mn;
            const unsigned long long cc = pk2(corr, corr);
#pragma unroll
            for (int j = 0; j < 4; j++) mul2(O2[i][j], cc);
            *(float4*)&Ps[(qb + i) * BN + kb] = make_float4(p0, p1, p2, p3);
        }
        __syncthreads();

        // ---- PV: O[8 queries][8 dims] += P[.][k] * V[k][.] ----
        const int db = tx * 8;
#pragma unroll 4
        for (int k = 0; k < BN; k++) {
            const float4 v0 = *(const float4*)&Vs[k * Hh + db];
            const float4 v1 = *(const float4*)&Vs[k * Hh + db + 4];
            const unsigned long long v01 = pk2(v0.x, v0.y);
            const unsigned long long v23 = pk2(v0.z, v0.w);
            const unsigned long long v45 = pk2(v1.x, v1.y);
            const unsigned long long v67 = pk2(v1.z, v1.w);
#pragma unroll
            for (int i = 0; i < 8; i++) {
                const float p = Ps[(qb + i) * BN + k];
                const unsigned long long pp = pk2(p, p);
                fma2(O2[i][0], pp, v01);
                fma2(O2[i][1], pp, v23);
                fma2(O2[i][2], pp, v45);
                fma2(O2[i][3], pp, v67);
            }
        }
    }

    // ---- epilogue: O /= l, write out ----
#pragma unroll
    for (int i = 0; i < 8; i++) {
        const float inv = 1.f / l[i];
        const float2 o0 = upk2(O2[i][0]);
        const float2 o1 = upk2(O2[i][1]);
        const float2 o2 = upk2(O2[i][2]);
        const float2 o3 = upk2(O2[i][3]);
        const float4 r0 = make_float4(o0.x * inv, o0.y * inv, o1.x * inv, o1.y * inv);
        const float4 r1 = make_float4(o2.x * inv, o2.y * inv, o3.x * inv, o3.y * inv);
        const size_t base = ((size_t)b * Tt + q0 + qb + i) * Hh + tx * 8;
        *(float4*)(out + base) = r0;
        *(float4*)(out + base + 4) = r1;
    }
}

extern "C" void kernel_launch(void* const* d_in, const int* in_sizes, int n_in,
                              void* d_out, int out_size) {
    const float* x  = (const float*)d_in[0];
    const float* Wk = (const float*)d_in[1];
    const float* Wq = (const float*)d_in[2];
    const float* Wv = (const float*)d_in[3];
    float* out = (float*)d_out;

    dim3 pg(Bb * Tt / PROJ_ROWS, 3);
    proj_kernel<<<pg, 128>>>(x, Wk, Wq, Wv);

    const size_t smem =
        (size_t)(BM * Hh + Hh * KS_STRIDE + BN * Hh + BM * BN) * sizeof(float);
    (void)cudaFuncSetAttribute(attn_kernel,
                               cudaFuncAttributeMaxDynamicSharedMemorySize,
                               (int)smem);
    dim3 ag(Tt / BM, Bb);
    attn_kernel<<<ag, NTH, smem>>>(out);
}